// round 1
// baseline (speedup 1.0000x reference)
#include <cuda_runtime.h>
#include <cstdint>

// Problem dims
#define M_DIM 32       // B*C
#define K_DIM 16384    // ROWS*COLS
#define N_DIM 16384    // H*W
#define KC    256      // k-chunk per CTA (smem x chunk = 256*32*4B = 32KB)
#define NTILE 512      // n per CTA (128 nq-threads * float4)
#define THREADS 256

// Scratch: transposed, relu'd, pre-scaled x. [k][m] layout, 2 MB.
__device__ float g_xT[K_DIM * M_DIM];

// ---------- packed f32x2 helpers ----------
__device__ __forceinline__ unsigned long long bcast2(float v) {
    unsigned long long r;
    asm("mov.b64 %0, {%1, %1};" : "=l"(r) : "f"(v));
    return r;
}
__device__ __forceinline__ unsigned long long fma2(unsigned long long a,
                                                   unsigned long long b,
                                                   unsigned long long c) {
    unsigned long long d;
    asm("fma.rn.f32x2 %0, %1, %2, %3;" : "=l"(d) : "l"(a), "l"(b), "l"(c));
    return d;
}

// ---------- kernel 1: zero the (poisoned) output ----------
__global__ void zero_out_kernel(float4* out) {
    int i = blockIdx.x * blockDim.x + threadIdx.x;   // 131072 float4 total
    out[i] = make_float4(0.f, 0.f, 0.f, 0.f);
}

// ---------- kernel 2: xT[k][m] = relu(image[m][k]) / 128 ----------
__global__ void prep_xt_kernel(const float* __restrict__ img) {
    int i = blockIdx.x * blockDim.x + threadIdx.x;   // 524288 total
    int m = i >> 14;          // /16384
    int k = i & (K_DIM - 1);
    float v = img[i];
    g_xT[k * M_DIM + m] = fmaxf(v, 0.f) * (1.0f / 128.0f);
}

// ---------- kernel 3: main sparse-skip GEMM ----------
// grid: (N_DIM/NTILE = 32, K_DIM/KC = 64), 256 threads
// thread t: mg = t>>7 (m-group of 16), nq = t&127 (float4 column in n-tile)
__global__ __launch_bounds__(THREADS)
void hough_kernel(const float* __restrict__ V, float* __restrict__ out) {
    __shared__ float sx[KC * M_DIM];   // 32 KB

    const int nb  = blockIdx.x;
    const int kb  = blockIdx.y;
    const int tid = threadIdx.x;
    const int mg  = tid >> 7;      // 0..1
    const int nq  = tid & 127;     // 0..127
    const int k0  = kb * KC;

    // Cooperative, fully coalesced smem fill of the x chunk (32 KB contiguous)
    {
        const float4* src = (const float4*)(g_xT + (size_t)k0 * M_DIM);
        float4* dst = (float4*)sx;
        #pragma unroll
        for (int i = tid; i < KC * M_DIM / 4; i += THREADS) dst[i] = src[i];
    }
    __syncthreads();

    // 4 n-subcolumns x 8 m-pairs of packed f32x2 accumulators
    unsigned long long acc[4][8];
    #pragma unroll
    for (int c = 0; c < 4; ++c)
        #pragma unroll
        for (int j = 0; j < 8; ++j) acc[c][j] = 0ULL;

    const float4* __restrict__ Vp =
        (const float4*)V + (size_t)k0 * (N_DIM / 4) + nb * (NTILE / 4) + nq;

    float4 v = Vp[0];

#define DO_COMP(comp, row)                                                   \
    if ((comp) != 0.0f) {                                                    \
        unsigned long long b = bcast2(comp);                                 \
        _Pragma("unroll")                                                    \
        for (int j = 0; j < 8; ++j) acc[row][j] = fma2(xs[j], b, acc[row][j]); \
    }

    #pragma unroll 2
    for (int k = 0; k < KC; ++k) {
        // prefetch next row (clamped so the last iteration stays in-bounds)
        int kn = (k + 1 < KC) ? (k + 1) : k;
        float4 vn = Vp[(size_t)kn * (N_DIM / 4)];

        const unsigned long long* xs =
            (const unsigned long long*)(sx + (k << 5) + (mg << 4));

        DO_COMP(v.x, 0)
        DO_COMP(v.y, 1)
        DO_COMP(v.z, 2)
        DO_COMP(v.w, 3)

        v = vn;
    }
#undef DO_COMP

    // Epilogue: split-K combine via atomics
    const int n0 = nb * NTILE + nq * 4;
    #pragma unroll
    for (int c = 0; c < 4; ++c) {
        #pragma unroll
        for (int j = 0; j < 8; ++j) {
            float lo = __uint_as_float((unsigned)(acc[c][j] & 0xffffffffULL));
            float hi = __uint_as_float((unsigned)(acc[c][j] >> 32));
            int m = (mg << 4) + 2 * j;
            atomicAdd(&out[(size_t)m * N_DIM + n0 + c], lo);
            atomicAdd(&out[(size_t)(m + 1) * N_DIM + n0 + c], hi);
        }
    }
}

extern "C" void kernel_launch(void* const* d_in, const int* in_sizes, int n_in,
                              void* d_out, int out_size) {
    const float* img = (const float*)d_in[0];   // (2,16,128,128) fp32
    const float* V   = (const float*)d_in[1];   // (128,128,128,128) fp32
    float* out = (float*)d_out;                 // (2,16,128,128) fp32

    (void)in_sizes; (void)n_in; (void)out_size;

    // out is poisoned -> zero it (524288 floats = 131072 float4)
    zero_out_kernel<<<512, 256>>>((float4*)out);

    // build xT (relu + /128 folded in)
    prep_xt_kernel<<<K_DIM * M_DIM / 256, 256>>>(img);

    dim3 grid(N_DIM / NTILE, K_DIM / KC);   // (32, 64)
    hough_kernel<<<grid, THREADS>>>(V, out);
}

// round 3
// speedup vs baseline: 2.7572x; 2.7572x over previous
#include <cuda_runtime.h>
#include <cstdint>

#define M_DIM 32
#define K_DIM 16384
#define N_DIM 16384
#define WORDS_PER_ROW (N_DIM / 32)   // 512
#define SPLITS 8
#define KSPLIT (K_DIM / SPLITS)      // 2048
#define KC 256
#define NB_TILE 256
#define PADX 34                      // floats per k-row in smem (136B: 8-aligned, bank-stride 2)
#define PADW 9                       // words per k-row in smem

// Static scratch (no allocation allowed)
__device__ float    g_xT[K_DIM * M_DIM];                 // 2 MB, xT[k][m] = relu(img)/128
__device__ unsigned g_bm[K_DIM * WORDS_PER_ROW];         // 32 MB bitmask, n-packed
__device__ float    g_part[SPLITS * M_DIM * N_DIM];      // 16 MB split-K partials

// ---------- packed f32x2 add ----------
__device__ __forceinline__ unsigned long long add2(unsigned long long a,
                                                   unsigned long long b) {
    unsigned long long d;
    asm("add.rn.f32x2 %0, %1, %2;" : "=l"(d) : "l"(a), "l"(b));
    return d;
}

// ---------- kernel 1: xT[k][m] = relu(image[m][k]) / 128 ----------
__global__ void prep_xt_kernel(const float* __restrict__ img) {
    int i = blockIdx.x * blockDim.x + threadIdx.x;   // 524288
    int m = i >> 14;
    int k = i & (K_DIM - 1);
    float v = img[i];
    g_xT[k * M_DIM + m] = fmaxf(v, 0.f) * (1.0f / 128.0f);
}

// ---------- kernel 2: compress V (fp32 0/1) -> bitmask, pure stream ----------
// thread: 8 consecutive elems (2x uint4 = 32B); 4 threads -> one u32 word
__global__ void bitmask_kernel(const uint4* __restrict__ V) {
    unsigned t = blockIdx.x * blockDim.x + threadIdx.x;   // 32M threads
    uint4 a = V[2 * (size_t)t];
    uint4 b = V[2 * (size_t)t + 1];
    unsigned bits =
        (unsigned)(a.x != 0u)        | ((unsigned)(a.y != 0u) << 1) |
        ((unsigned)(a.z != 0u) << 2) | ((unsigned)(a.w != 0u) << 3) |
        ((unsigned)(b.x != 0u) << 4) | ((unsigned)(b.y != 0u) << 5) |
        ((unsigned)(b.z != 0u) << 6) | ((unsigned)(b.w != 0u) << 7);
    unsigned sub = threadIdx.x & 3;
    unsigned v = bits << (sub * 8);
    v |= __shfl_xor_sync(0xffffffffu, v, 1);
    v |= __shfl_xor_sync(0xffffffffu, v, 2);
    if (sub == 0) g_bm[t >> 2] = v;
}

// ---------- kernel 3: sparse accumulate via bit-transpose + ffs ----------
// grid (64 n-tiles, 8 k-splits), 256 threads; warp w owns n = nb*256+w*32+lane
__global__ __launch_bounds__(256)
void spmm_kernel() {
    __shared__ __align__(16) float    sx[KC * PADX];      // ~34.8 KB
    __shared__ __align__(16) unsigned swd[KC * PADW];     // ~9.2 KB

    const int nb = blockIdx.x, kb = blockIdx.y;
    const int tid = threadIdx.x, w = tid >> 5, lane = tid & 31;

    unsigned long long acc[16];
    #pragma unroll
    for (int q = 0; q < 16; ++q) acc[q] = 0ull;

    for (int c = 0; c < KSPLIT / KC; ++c) {
        const int k0 = kb * KSPLIT + c * KC;
        __syncthreads();
        // stage x chunk: float2 stores (row byte stride 136 is 8-aligned)
        {
            const float2* src = (const float2*)(g_xT + (size_t)k0 * M_DIM);
            for (int i = tid; i < KC * 16; i += 256) {
                int kk = i >> 4, q = i & 15;
                *(float2*)(sx + kk * PADX + q * 2) = src[i];
            }
        }
        // stage bitmask words: 8 n-words per k for this CTA's 256 n
        {
            const unsigned* wsrc = g_bm + (size_t)k0 * WORDS_PER_ROW + nb * 8;
            for (int i = tid; i < KC * 8; i += 256) {
                int kk = i >> 3, q = i & 7;
                swd[kk * PADW + q] = wsrc[(size_t)kk * WORDS_PER_ROW + q];
            }
        }
        __syncthreads();

        #pragma unroll 1
        for (int t32 = 0; t32 < KC / 32; ++t32) {
            // lane holds n-bits of row k = base + lane
            unsigned x = swd[(t32 * 32 + lane) * PADW + w];
            // 32x32 bit transpose: after this, lane holds k-bits of its n
            #pragma unroll
            for (int d = 16; d >= 1; d >>= 1) {
                const unsigned A = (d == 16) ? 0xFFFF0000u :
                                   (d == 8)  ? 0xFF00FF00u :
                                   (d == 4)  ? 0xF0F0F0F0u :
                                   (d == 2)  ? 0xCCCCCCCCu : 0xAAAAAAAAu;
                unsigned y = __shfl_xor_sync(0xffffffffu, x, d);
                x = (lane & d) ? ((x & A) | ((y >> d) & ~A))
                               : ((x & ~A) | ((y << d) & A));
            }
            // iterate this lane's set k-bits only
            while (x) {
                int j = __ffs(x) - 1;
                x &= x - 1;
                const unsigned long long* xs =
                    (const unsigned long long*)(sx + (t32 * 32 + j) * PADX);
                #pragma unroll
                for (int q = 0; q < 16; ++q) acc[q] = add2(acc[q], xs[q]);
            }
        }
    }

    // write split-K partials (covers every (m,n) -> no zero-init needed)
    const int n = nb * NB_TILE + w * 32 + lane;
    float* po = g_part + (size_t)kb * (M_DIM * N_DIM);
    #pragma unroll
    for (int q = 0; q < 16; ++q) {
        unsigned lo = (unsigned)(acc[q] & 0xffffffffull);
        unsigned hi = (unsigned)(acc[q] >> 32);
        po[(size_t)(2 * q) * N_DIM + n]     = __uint_as_float(lo);
        po[(size_t)(2 * q + 1) * N_DIM + n] = __uint_as_float(hi);
    }
}

// ---------- kernel 4: reduce split-K partials into d_out ----------
__global__ void reduce_kernel(float4* __restrict__ out) {
    int i = blockIdx.x * blockDim.x + threadIdx.x;   // 131072 float4
    const float4* p = (const float4*)g_part;
    float4 s = p[i];
    #pragma unroll
    for (int sp = 1; sp < SPLITS; ++sp) {
        float4 v = p[(size_t)sp * (M_DIM * N_DIM / 4) + i];
        s.x += v.x; s.y += v.y; s.z += v.z; s.w += v.w;
    }
    out[i] = s;
}

extern "C" void kernel_launch(void* const* d_in, const int* in_sizes, int n_in,
                              void* d_out, int out_size) {
    const float* img = (const float*)d_in[0];   // (2,16,128,128)
    const uint4* V   = (const uint4*)d_in[1];   // (128,128,128,128) as bits
    float* out = (float*)d_out;

    (void)in_sizes; (void)n_in; (void)out_size;

    prep_xt_kernel<<<(K_DIM * M_DIM) / 256, 256>>>(img);
    bitmask_kernel<<<(K_DIM * N_DIM / 8) / 256, 256>>>(V);

    dim3 grid(N_DIM / NB_TILE, SPLITS);   // (64, 8)
    spmm_kernel<<<grid, 256>>>();

    reduce_kernel<<<(M_DIM * N_DIM / 4) / 256, 256>>>((float4*)out);
}